// round 3
// baseline (speedup 1.0000x reference)
#include <cuda_runtime.h>

// Problem constants
#define B_SAMPLES  4096
#define D_DIM      768
#define N_CLASSES  1000
#define MAX_STAGES 4
#define MAX_P      8
#define SHARED_P   16

#define D_VEC (D_DIM / 4)        // 192 float4 per row

// Scratch (allocation-free)
__device__ float g_shared_mean[MAX_STAGES * D_DIM];
__device__ int2  g_desc[B_SAMPLES];   // {pair_idx = cid*4+st, cnt}

// ---------------------------------------------------------------------------
// Prep kernel: grid = 20 blocks x 256 threads.
//   blocks 0..15 : pack descriptors (256 samples each)
//   blocks 16..19: shared_mean for stage (blockIdx-16)
// ---------------------------------------------------------------------------
__global__ __launch_bounds__(256)
void prep_kernel(const float* __restrict__ shared_protos,
                 const int*   __restrict__ class_ids,
                 const int*   __restrict__ stages,
                 const int*   __restrict__ proto_counts) {
    int blk = blockIdx.x;
    int t   = threadIdx.x;

    if (blk < 16) {
        int b = blk * 256 + t;
        int cid  = class_ids[b];
        int st   = stages[b];
        int pair = cid * MAX_STAGES + st;
        int cnt  = proto_counts[pair];
        g_desc[b] = make_int2(pair, cnt);
    } else {
        int st = blk - 16;
        if (t < D_VEC) {
            const float4* src = reinterpret_cast<const float4*>(
                shared_protos + (size_t)st * SHARED_P * D_DIM);
            float4 acc = make_float4(0.f, 0.f, 0.f, 0.f);
#pragma unroll
            for (int p = 0; p < SHARED_P; ++p) {
                float4 x = src[p * D_VEC + t];
                acc.x += x.x; acc.y += x.y; acc.z += x.z; acc.w += x.w;
            }
            const float inv = 1.0f / (float)SHARED_P;
            acc.x *= inv; acc.y *= inv; acc.z *= inv; acc.w *= inv;
            reinterpret_cast<float4*>(g_shared_mean)[st * D_VEC + t] = acc;
        }
    }
}

// ---------------------------------------------------------------------------
// Main kernel: one block per sample, 192 threads (one float4 lane each).
// All 8 proto loads batched into registers (8-deep MLP per thread).
// ---------------------------------------------------------------------------
__global__ __launch_bounds__(D_VEC)
void proto_pool_kernel(const float* __restrict__ features,
                       const float* __restrict__ class_protos,
                       float* __restrict__ out) {
    int b = blockIdx.x;
    int v = threadIdx.x;

    // Independent: feature load first (streaming — no reuse)
    float4 f = __ldcs(reinterpret_cast<const float4*>(features) + (size_t)b * D_VEC + v);

    // Warp-uniform descriptor (single L1-broadcast load)
    int2 dd  = g_desc[b];
    int pair = dd.x;
    int cnt  = dd.y;
    int st   = pair & 3;

    float4 sh = reinterpret_cast<const float4*>(g_shared_mean)[st * D_VEC + v];

    const float4* __restrict__ protos =
        reinterpret_cast<const float4*>(class_protos) +
        (size_t)pair * (MAX_P * D_VEC) + v;

    // Batched predicated loads: all 8 issue back-to-back, zero-fill past cnt.
    float4 x[MAX_P];
#pragma unroll
    for (int p = 0; p < MAX_P; ++p) {
        x[p] = (p < cnt) ? protos[p * D_VEC] : make_float4(0.f, 0.f, 0.f, 0.f);
    }

    // Tree sum
#pragma unroll
    for (int s = MAX_P / 2; s > 0; s >>= 1) {
#pragma unroll
        for (int p = 0; p < s; ++p) {
            x[p].x += x[p + s].x; x[p].y += x[p + s].y;
            x[p].z += x[p + s].z; x[p].w += x[p + s].w;
        }
    }

    float inv = 0.5f / (float)max(cnt, 1);   // fold the 0.5 into the mean

    float4 r;
    r.x = f.x + 0.5f * sh.x + x[0].x * inv;
    r.y = f.y + 0.5f * sh.y + x[0].y * inv;
    r.z = f.z + 0.5f * sh.z + x[0].z * inv;
    r.w = f.w + 0.5f * sh.w + x[0].w * inv;

    __stcs(reinterpret_cast<float4*>(out) + (size_t)b * D_VEC + v, r);
}

extern "C" void kernel_launch(void* const* d_in, const int* in_sizes, int n_in,
                              void* d_out, int out_size) {
    const float* features      = (const float*)d_in[0];
    const float* class_protos  = (const float*)d_in[1];
    const float* shared_protos = (const float*)d_in[2];
    const int*   class_ids     = (const int*)d_in[3];
    const int*   stages        = (const int*)d_in[4];
    const int*   proto_counts  = (const int*)d_in[5];
    float* out = (float*)d_out;

    prep_kernel<<<20, 256>>>(shared_protos, class_ids, stages, proto_counts);
    proto_pool_kernel<<<B_SAMPLES, D_VEC>>>(features, class_protos, out);
}

// round 4
// speedup vs baseline: 1.0025x; 1.0025x over previous
#include <cuda_runtime.h>
#include <cstdint>

// Problem constants
#define B_SAMPLES  4096
#define D_DIM      768
#define N_CLASSES  1000
#define MAX_STAGES 4
#define MAX_P      8
#define SHARED_P   16

#define D_VEC (D_DIM / 4)          // 192 float4 per row
#define ROW_BYTES (D_DIM * 4)      // 3072 bytes per proto row

// Scratch (allocation-free)
__device__ float g_shared_mean[MAX_STAGES * D_DIM];
__device__ int2  g_desc[B_SAMPLES];   // {pair_idx = cid*4+st, cnt}

// ---------------------------------------------------------------------------
// Prep kernel: pack per-sample descriptors + shared-stage means.
// ---------------------------------------------------------------------------
__global__ __launch_bounds__(256)
void prep_kernel(const float* __restrict__ shared_protos,
                 const int*   __restrict__ class_ids,
                 const int*   __restrict__ stages,
                 const int*   __restrict__ proto_counts) {
    int blk = blockIdx.x;
    int t   = threadIdx.x;

    if (blk < 16) {
        int b = blk * 256 + t;
        int cid  = class_ids[b];
        int st   = stages[b];
        int pair = cid * MAX_STAGES + st;
        int cnt  = proto_counts[pair];
        g_desc[b] = make_int2(pair, cnt);
    } else {
        int st = blk - 16;
        if (t < D_VEC) {
            const float4* src = reinterpret_cast<const float4*>(
                shared_protos + (size_t)st * SHARED_P * D_DIM);
            float4 acc = make_float4(0.f, 0.f, 0.f, 0.f);
#pragma unroll
            for (int p = 0; p < SHARED_P; ++p) {
                float4 x = src[p * D_VEC + t];
                acc.x += x.x; acc.y += x.y; acc.z += x.z; acc.w += x.w;
            }
            const float inv = 1.0f / (float)SHARED_P;
            acc.x *= inv; acc.y *= inv; acc.z *= inv; acc.w *= inv;
            reinterpret_cast<float4*>(g_shared_mean)[st * D_VEC + t] = acc;
        }
    }
}

__device__ __forceinline__ uint32_t smem_u32(const void* p) {
    uint32_t a;
    asm("{ .reg .u64 t; cvta.to.shared.u64 t, %1; cvt.u32.u64 %0, t; }"
        : "=r"(a) : "l"(p));
    return a;
}

// ---------------------------------------------------------------------------
// Main kernel: one block per sample, 192 threads.
// Proto gather via ONE cp.async.bulk (G->SMEM, cnt*3072 bytes), reduce via LDS.
// ---------------------------------------------------------------------------
__global__ __launch_bounds__(D_VEC)
void proto_pool_kernel(const float* __restrict__ features,
                       const float* __restrict__ class_protos,
                       float* __restrict__ out) {
    __shared__ __align__(16) float4 s_protos[MAX_P * D_VEC];   // 24 KB
    __shared__ __align__(8)  uint64_t s_mbar;

    int b = blockIdx.x;
    int v = threadIdx.x;

    // Per-sample descriptor (warp-broadcast load, L2-resident after first wave)
    int2 dd  = g_desc[b];
    int pair = dd.x;
    int cnt  = dd.y;
    int st   = pair & 3;

    uint32_t mbar = smem_u32(&s_mbar);
    if (v == 0) {
        asm volatile("mbarrier.init.shared.b64 [%0], 1;" :: "r"(mbar) : "memory");
    }
    __syncthreads();

    if (cnt > 0 && v == 0) {
        uint32_t bytes = (uint32_t)cnt * ROW_BYTES;
        const char* gsrc = reinterpret_cast<const char*>(class_protos) +
                           (size_t)pair * (MAX_P * ROW_BYTES);
        uint32_t dst = smem_u32(s_protos);
        asm volatile("mbarrier.arrive.expect_tx.shared.b64 _, [%0], %1;"
                     :: "r"(mbar), "r"(bytes) : "memory");
        asm volatile(
            "cp.async.bulk.shared::cta.global.mbarrier::complete_tx::bytes "
            "[%0], [%1], %2, [%3];"
            :: "r"(dst), "l"(gsrc), "r"(bytes), "r"(mbar) : "memory");
    }

    // Independent loads while the bulk copy is in flight
    float4 f  = __ldcs(reinterpret_cast<const float4*>(features) +
                       (size_t)b * D_VEC + v);
    float4 sh = reinterpret_cast<const float4*>(g_shared_mean)[st * D_VEC + v];

    float4 a0 = make_float4(0.f, 0.f, 0.f, 0.f);
    float4 a1 = make_float4(0.f, 0.f, 0.f, 0.f);

    if (cnt > 0) {
        // Wait for bulk copy completion (phase parity 0 — barrier used once)
        uint32_t done;
        asm volatile(
            "{\n\t"
            ".reg .pred p;\n\t"
            "mbarrier.try_wait.parity.acquire.cta.shared::cta.b64 p, [%1], 0;\n\t"
            "selp.b32 %0, 1, 0, p;\n\t"
            "}" : "=r"(done) : "r"(mbar) : "memory");
        if (!done) {
            asm volatile(
                "{\n\t"
                ".reg .pred P1;\n\t"
                "W_%=:\n\t"
                "mbarrier.try_wait.parity.acquire.cta.shared::cta.b64 P1, [%0], 0, 0x989680;\n\t"
                "@P1 bra.uni D_%=;\n\t"
                "bra.uni W_%=;\n\t"
                "D_%=:\n\t"
                "}" :: "r"(mbar) : "memory");
        }

        // Reduce cnt rows from SMEM (conflict-free LDS.128), 2 accumulators
        int p = 0;
        for (; p + 1 < cnt; p += 2) {
            float4 x0 = s_protos[p * D_VEC + v];
            float4 x1 = s_protos[(p + 1) * D_VEC + v];
            a0.x += x0.x; a0.y += x0.y; a0.z += x0.z; a0.w += x0.w;
            a1.x += x1.x; a1.y += x1.y; a1.z += x1.z; a1.w += x1.w;
        }
        if (p < cnt) {
            float4 x0 = s_protos[p * D_VEC + v];
            a0.x += x0.x; a0.y += x0.y; a0.z += x0.z; a0.w += x0.w;
        }
    }

    float inv = 0.5f / (float)max(cnt, 1);   // fold the 0.5 into the mean

    float4 r;
    r.x = f.x + 0.5f * sh.x + (a0.x + a1.x) * inv;
    r.y = f.y + 0.5f * sh.y + (a0.y + a1.y) * inv;
    r.z = f.z + 0.5f * sh.z + (a0.z + a1.z) * inv;
    r.w = f.w + 0.5f * sh.w + (a0.w + a1.w) * inv;

    __stcs(reinterpret_cast<float4*>(out) + (size_t)b * D_VEC + v, r);
}

extern "C" void kernel_launch(void* const* d_in, const int* in_sizes, int n_in,
                              void* d_out, int out_size) {
    const float* features      = (const float*)d_in[0];
    const float* class_protos  = (const float*)d_in[1];
    const float* shared_protos = (const float*)d_in[2];
    const int*   class_ids     = (const int*)d_in[3];
    const int*   stages        = (const int*)d_in[4];
    const int*   proto_counts  = (const int*)d_in[5];
    float* out = (float*)d_out;

    prep_kernel<<<20, 256>>>(shared_protos, class_ids, stages, proto_counts);
    proto_pool_kernel<<<B_SAMPLES, D_VEC>>>(features, class_protos, out);
}

// round 5
// speedup vs baseline: 1.0149x; 1.0124x over previous
#include <cuda_runtime.h>
#include <cstdint>

// Problem constants
#define B_SAMPLES  4096
#define D_DIM      768
#define N_CLASSES  1000
#define MAX_STAGES 4
#define MAX_P      8
#define SHARED_P   16

#define D_VEC (D_DIM / 4)          // 192 float4 per row
#define ROW_BYTES (D_DIM * 4)      // 3072 bytes per proto row
#define SPB 4                      // samples per block
#define NBLK (B_SAMPLES / SPB)     // 1024
#define BUF_F4 (MAX_P * D_VEC)     // 1536 float4 per buffer (24 KB)
#define SMEM_BYTES (2 * BUF_F4 * 16)

// Scratch (allocation-free)
__device__ float g_shared_mean[MAX_STAGES * D_DIM];
__device__ int2  g_desc[B_SAMPLES];   // {pair_idx = cid*4+st, cnt}

// ---------------------------------------------------------------------------
// Prep kernel: pack per-sample descriptors + shared-stage means.
// ---------------------------------------------------------------------------
__global__ __launch_bounds__(256)
void prep_kernel(const float* __restrict__ shared_protos,
                 const int*   __restrict__ class_ids,
                 const int*   __restrict__ stages,
                 const int*   __restrict__ proto_counts) {
    int blk = blockIdx.x;
    int t   = threadIdx.x;

    if (blk < 16) {
        int b = blk * 256 + t;
        int cid  = class_ids[b];
        int st   = stages[b];
        int pair = cid * MAX_STAGES + st;
        int cnt  = proto_counts[pair];
        g_desc[b] = make_int2(pair, cnt);
    } else {
        int st = blk - 16;
        if (t < D_VEC) {
            const float4* src = reinterpret_cast<const float4*>(
                shared_protos + (size_t)st * SHARED_P * D_DIM);
            float4 acc = make_float4(0.f, 0.f, 0.f, 0.f);
#pragma unroll
            for (int p = 0; p < SHARED_P; ++p) {
                float4 x = src[p * D_VEC + t];
                acc.x += x.x; acc.y += x.y; acc.z += x.z; acc.w += x.w;
            }
            const float inv = 1.0f / (float)SHARED_P;
            acc.x *= inv; acc.y *= inv; acc.z *= inv; acc.w *= inv;
            reinterpret_cast<float4*>(g_shared_mean)[st * D_VEC + t] = acc;
        }
    }
}

__device__ __forceinline__ uint32_t smem_u32(const void* p) {
    uint32_t a;
    asm("{ .reg .u64 t; cvta.to.shared.u64 t, %1; cvt.u32.u64 %0, t; }"
        : "=r"(a) : "l"(p));
    return a;
}

__device__ __forceinline__ void mbar_wait(uint32_t mbar, uint32_t parity) {
    uint32_t done;
    asm volatile(
        "{\n\t"
        ".reg .pred p;\n\t"
        "mbarrier.try_wait.parity.acquire.cta.shared::cta.b64 p, [%1], %2;\n\t"
        "selp.b32 %0, 1, 0, p;\n\t"
        "}" : "=r"(done) : "r"(mbar), "r"(parity) : "memory");
    if (!done) {
        asm volatile(
            "{\n\t"
            ".reg .pred P1;\n\t"
            "W_%=:\n\t"
            "mbarrier.try_wait.parity.acquire.cta.shared::cta.b64 P1, [%0], %1, 0x989680;\n\t"
            "@P1 bra.uni D_%=;\n\t"
            "bra.uni W_%=;\n\t"
            "D_%=:\n\t"
            "}" :: "r"(mbar), "r"(parity) : "memory");
    }
}

// Issue bulk copy of sample's protos into buffer (thread 0 of block only).
// If cnt == 0, performs a plain arrive so the barrier phase still flips.
__device__ __forceinline__ void issue_copy(uint32_t mbar, uint32_t dst,
                                           const float* class_protos,
                                           int pair, int cnt) {
    if (cnt > 0) {
        uint32_t bytes = (uint32_t)cnt * ROW_BYTES;
        const char* gsrc = reinterpret_cast<const char*>(class_protos) +
                           (size_t)pair * (MAX_P * ROW_BYTES);
        asm volatile("mbarrier.arrive.expect_tx.shared.b64 _, [%0], %1;"
                     :: "r"(mbar), "r"(bytes) : "memory");
        asm volatile(
            "cp.async.bulk.shared::cta.global.mbarrier::complete_tx::bytes "
            "[%0], [%1], %2, [%3];"
            :: "r"(dst), "l"(gsrc), "r"(bytes), "r"(mbar) : "memory");
    } else {
        asm volatile("mbarrier.arrive.shared.b64 _, [%0];"
                     :: "r"(mbar) : "memory");
    }
}

// ---------------------------------------------------------------------------
// Main kernel: 4 samples per block, double-buffered bulk copies.
// ---------------------------------------------------------------------------
__global__ __launch_bounds__(D_VEC)
void proto_pool_kernel(const float* __restrict__ features,
                       const float* __restrict__ class_protos,
                       float* __restrict__ out) {
    extern __shared__ __align__(16) float4 sbuf[];   // 2 x 24 KB
    __shared__ __align__(8) uint64_t s_mbar[2];

    int base = blockIdx.x;          // samples: base + k*NBLK
    int v    = threadIdx.x;

    // Descriptors for all 4 samples up front (broadcast loads)
    int2 dd[SPB];
#pragma unroll
    for (int k = 0; k < SPB; ++k) dd[k] = g_desc[base + k * NBLK];

    uint32_t mbar0 = smem_u32(&s_mbar[0]);
    uint32_t mbar1 = smem_u32(&s_mbar[1]);
    uint32_t buf0  = smem_u32(&sbuf[0]);
    uint32_t buf1  = smem_u32(&sbuf[BUF_F4]);

    if (v == 0) {
        asm volatile("mbarrier.init.shared.b64 [%0], 1;" :: "r"(mbar0) : "memory");
        asm volatile("mbarrier.init.shared.b64 [%0], 1;" :: "r"(mbar1) : "memory");
    }
    __syncthreads();

    if (v == 0) {
        issue_copy(mbar0, buf0, class_protos, dd[0].x, dd[0].y);
        issue_copy(mbar1, buf1, class_protos, dd[1].x, dd[1].y);
    }

#pragma unroll
    for (int k = 0; k < SPB; ++k) {
        int sample = base + k * NBLK;
        int pair = dd[k].x;
        int cnt  = dd[k].y;
        int st   = pair & 3;
        uint32_t mbar = (k & 1) ? mbar1 : mbar0;
        const float4* buf = (k & 1) ? (sbuf + BUF_F4) : sbuf;
        uint32_t parity = (k >> 1) & 1;

        // Independent global loads while the copy is in flight
        float4 f  = __ldcs(reinterpret_cast<const float4*>(features) +
                           (size_t)sample * D_VEC + v);
        float4 sh = reinterpret_cast<const float4*>(g_shared_mean)[st * D_VEC + v];

        mbar_wait(mbar, parity);

        float4 a0 = make_float4(0.f, 0.f, 0.f, 0.f);
        float4 a1 = make_float4(0.f, 0.f, 0.f, 0.f);
        int p = 0;
        for (; p + 1 < cnt; p += 2) {
            float4 x0 = buf[p * D_VEC + v];
            float4 x1 = buf[(p + 1) * D_VEC + v];
            a0.x += x0.x; a0.y += x0.y; a0.z += x0.z; a0.w += x0.w;
            a1.x += x1.x; a1.y += x1.y; a1.z += x1.z; a1.w += x1.w;
        }
        if (p < cnt) {
            float4 x0 = buf[p * D_VEC + v];
            a0.x += x0.x; a0.y += x0.y; a0.z += x0.z; a0.w += x0.w;
        }

        float inv = 0.5f / (float)max(cnt, 1);
        float4 r;
        r.x = f.x + 0.5f * sh.x + (a0.x + a1.x) * inv;
        r.y = f.y + 0.5f * sh.y + (a0.y + a1.y) * inv;
        r.z = f.z + 0.5f * sh.z + (a0.z + a1.z) * inv;
        r.w = f.w + 0.5f * sh.w + (a0.w + a1.w) * inv;
        __stcs(reinterpret_cast<float4*>(out) + (size_t)sample * D_VEC + v, r);

        // Refill this buffer for sample k+2 once all threads are done reading it
        if (k + 2 < SPB) {
            __syncthreads();
            if (v == 0) {
                uint32_t dst = (k & 1) ? buf1 : buf0;
                issue_copy(mbar, dst, class_protos, dd[k + 2].x, dd[k + 2].y);
            }
        }
    }
}

extern "C" void kernel_launch(void* const* d_in, const int* in_sizes, int n_in,
                              void* d_out, int out_size) {
    const float* features      = (const float*)d_in[0];
    const float* class_protos  = (const float*)d_in[1];
    const float* shared_protos = (const float*)d_in[2];
    const int*   class_ids     = (const int*)d_in[3];
    const int*   stages        = (const int*)d_in[4];
    const int*   proto_counts  = (const int*)d_in[5];
    float* out = (float*)d_out;

    static int smem_set = 0;
    if (!smem_set) {
        cudaFuncSetAttribute(proto_pool_kernel,
                             cudaFuncAttributeMaxDynamicSharedMemorySize,
                             SMEM_BYTES);
        smem_set = 1;
    }

    prep_kernel<<<20, 256>>>(shared_protos, class_ids, stages, proto_counts);
    proto_pool_kernel<<<NBLK, D_VEC, SMEM_BYTES>>>(features, class_protos, out);
}